// round 10
// baseline (speedup 1.0000x reference)
#include <cuda_runtime.h>
#include <math.h>

// ---------------------------------------------------------------------------
// SPDNet collapsed: out = vec(logm(M^T X M)) @ Wsym + b,  M = w1 @ w2 (12x11)
// Both ReEig stages are provably no-ops (lambda_min >= 1e-3 > eps = 1e-4).
// One-sided Jacobi SVD on the Cholesky factor G (H = G G^T), two-MUFU
// rotations. R10: one matrix is split across a LANE PAIR (lane, lane^1) --
// each thread holds half the rows of G (66 regs of state instead of 132),
// dots complete via SHFL.BFLY, (c,s) chains run redundantly (bitwise
// identical), the linear layer is split 26/26. Frees registers -> 3 blocks/SM.
// ---------------------------------------------------------------------------

#define NSWEEP 5
#define WSK 68   // padded inner dim for the linear layer (66 -> 68 for float4)

typedef unsigned long long ull;

__device__ float g_M[132];            // M = w1 @ w2 (12x11)
__device__ ull   g_M2[12 * 6];        // M rows packed as f32x2 (11 -> 12 padded)
__device__ float g_Wsym[52 * WSK];    // symmetrized linear weights, padded

// upper-triangle index, requires i <= j
__device__ __forceinline__ constexpr int TRI(int i, int j) {
    return i * 11 - (i * (i + 1)) / 2 + j;
}

// ---- packed f32x2 helpers (PTX-only; ptxas never fuses these from C++) ----
__device__ __forceinline__ ull pack2(float lo, float hi) {
    ull r; asm("mov.b64 %0, {%1, %2};" : "=l"(r) : "f"(lo), "f"(hi)); return r;
}
__device__ __forceinline__ void unpack2(ull v, float& lo, float& hi) {
    asm("mov.b64 {%0, %1}, %2;" : "=f"(lo), "=f"(hi) : "l"(v));
}
__device__ __forceinline__ ull fma2(ull a, ull b, ull c) {
    ull d; asm("fma.rn.f32x2 %0, %1, %2, %3;" : "=l"(d) : "l"(a), "l"(b), "l"(c)); return d;
}
__device__ __forceinline__ ull mul2(ull a, ull b) {
    ull d; asm("mul.rn.f32x2 %0, %1, %2;" : "=l"(d) : "l"(a), "l"(b)); return d;
}

__global__ void prep_kernel(const float* __restrict__ w1,
                            const float* __restrict__ w2,
                            const float* __restrict__ w_lin) {
    __shared__ float sM[132];
    int t = threadIdx.x;
    if (t < 132) {
        int i = t / 11, l = t % 11;
        float acc = 0.f;
        #pragma unroll
        for (int k = 0; k < 12; ++k) acc += w1[i * 12 + k] * w2[k * 11 + l];
        sM[t] = acc;
        g_M[t] = acc;
    }
    __syncthreads();
    if (t < 72) {
        int j = t / 6, rp = t % 6;
        float lo = (2 * rp     < 11) ? sM[j * 11 + 2 * rp]     : 0.f;
        float hi = (2 * rp + 1 < 11) ? sM[j * 11 + 2 * rp + 1] : 0.f;
        g_M2[t] = pack2(lo, hi);
    }
    for (int idx = t; idx < 52 * WSK; idx += blockDim.x) {
        int c = idx / WSK, tt = idx % WSK;
        float v = 0.f;
        if (tt < 66) {
            int i = 0, rem = tt;
            while (rem >= 11 - i) { rem -= 11 - i; ++i; }
            int j = i + rem;
            if (i == j) v = w_lin[c * 121 + i * 11 + i];
            else        v = w_lin[c * 121 + i * 11 + j] + w_lin[c * 121 + j * 11 + i];
        }
        g_Wsym[idx] = v;
    }
}

__global__ __launch_bounds__(128, 3) void spd_main(const float* __restrict__ x,
                                                   const float* __restrict__ b_lin,
                                                   float* __restrict__ out, int B) {
    __shared__ float Ms[132];
    __shared__ ull   Ms2[72];
    __shared__ alignas(16) float Ws[52 * WSK];
    __shared__ float bs[52];
    for (int i = threadIdx.x; i < 132; i += blockDim.x) Ms[i] = g_M[i];
    for (int i = threadIdx.x; i < 72; i += blockDim.x) Ms2[i] = g_M2[i];
    for (int i = threadIdx.x; i < 52 * WSK; i += blockDim.x) Ws[i] = g_Wsym[i];
    if (threadIdx.x < 52) bs[threadIdx.x] = b_lin[threadIdx.x];
    __syncthreads();

    const int tid  = threadIdx.x;
    const int half = tid & 1;                       // which row-half of G we own
    int bOrig = blockIdx.x * 64 + (tid >> 1);       // one matrix per lane PAIR
    const bool live = bOrig < B;
    int b = live ? bOrig : (B - 1);                 // clamp: keep all lanes active for shfl

    // ---- H = M^T X M (redundant in both pair threads), packed upper tri ----
    float h[66];
    #pragma unroll
    for (int k = 0; k < 66; ++k) h[k] = 0.f;

    const float4* xg = reinterpret_cast<const float4*>(x + (size_t)b * 144);
    #pragma unroll
    for (int i = 0; i < 12; ++i) {
        float4 v0 = xg[i * 3 + 0];
        float4 v1 = xg[i * 3 + 1];
        float4 v2 = xg[i * 3 + 2];
        float xr[12] = {v0.x, v0.y, v0.z, v0.w,
                        v1.x, v1.y, v1.z, v1.w,
                        v2.x, v2.y, v2.z, v2.w};
        ull trow2[6];
        {
            ull xj2 = pack2(xr[0], xr[0]);
            #pragma unroll
            for (int rp = 0; rp < 6; ++rp) trow2[rp] = mul2(xj2, Ms2[0 * 6 + rp]);
        }
        #pragma unroll
        for (int j = 1; j < 12; ++j) {
            ull xj2 = pack2(xr[j], xr[j]);
            #pragma unroll
            for (int rp = 0; rp < 6; ++rp)
                trow2[rp] = fma2(xj2, Ms2[j * 6 + rp], trow2[rp]);
        }
        float trow[12];
        #pragma unroll
        for (int rp = 0; rp < 6; ++rp) unpack2(trow2[rp], trow[2 * rp], trow[2 * rp + 1]);
        #pragma unroll
        for (int k = 0; k < 11; ++k) {
            float mik = Ms[i * 11 + k];
            #pragma unroll
            for (int l = k; l < 11; ++l)
                h[TRI(k, l)] = fmaf(mik, trow[l], h[TRI(k, l)]);
        }
    }

    // ---- Cholesky H = R^T R (redundant) fused with HALF-packing of G = R^T:
    //      this thread keeps only rows [half*6, half*6+6) of each column. ----
    ull g2h[11][3];
    float nrm[11];
    #pragma unroll
    for (int k = 0; k < 11; ++k) {
        float d   = fmaxf(h[TRI(k, k)], 1e-30f);
        float inv = rsqrtf(d);
        float rk[11];
        #pragma unroll
        for (int j = 0; j < 11; ++j) rk[j] = 0.f;
        rk[k] = d * inv;
        #pragma unroll
        for (int j = k + 1; j < 11; ++j) rk[j] = h[TRI(k, j)] * inv;
        float acc = d;
        #pragma unroll
        for (int j = k + 1; j < 11; ++j) acc = fmaf(rk[j], rk[j], acc);
        nrm[k] = acc;
        #pragma unroll
        for (int rp3 = 0; rp3 < 3; ++rp3) {
            // rp = half*3 + rp3; both index choices are compile-time, SEL at runtime
            float lo0 = rk[2 * rp3];
            float hi0 = rk[2 * rp3 + 1];
            float lo1 = rk[6 + 2 * rp3];
            float hi1 = (7 + 2 * rp3 < 11) ? rk[7 + 2 * rp3] : 0.f;
            g2h[k][rp3] = pack2(half ? lo1 : lo0, half ? hi1 : hi0);
        }
        #pragma unroll
        for (int j = k + 1; j < 11; ++j) {
            float a = rk[j];
            #pragma unroll
            for (int l = j; l < 11; ++l)
                h[TRI(j, l)] = fmaf(-a, rk[l], h[TRI(j, l)]);
        }
    }

    // ---- one-sided Jacobi on column halves; dot completed via SHFL.BFLY.
    //      (c,s) chain is computed redundantly in both threads -- bitwise
    //      identical since apq = ps + po is symmetric under exchange. ----
    for (int sweep = 0; sweep < NSWEEP; ++sweep) {
        #pragma unroll
        for (int r = 0; r < 11; ++r) {
            const int mm = (r * 6) % 11;  // bye element; pairs (mm+k, mm-k)
            #pragma unroll
            for (int k = 1; k <= 5; ++k) {
                const int a0 = (mm + k) % 11;
                const int b0 = (mm + 11 - k) % 11;
                const int p = (a0 < b0) ? a0 : b0;
                const int q = (a0 < b0) ? b0 : a0;
                ull acc = mul2(g2h[p][0], g2h[q][0]);
                acc = fma2(g2h[p][1], g2h[q][1], acc);
                acc = fma2(g2h[p][2], g2h[q][2], acc);
                float dlo, dhi;
                unpack2(acc, dlo, dhi);
                float ps = dlo + dhi;
                float po = __shfl_xor_sync(0xFFFFFFFFu, ps, 1);
                float apq = ps + po;
                float app = nrm[p], aqq = nrm[q];
                float dq   = aqq - app;
                float sum  = fmaf(dq, dq, 4.f * apq * apq);
                bool  ok   = sum > 1e-30f;
                float rr   = rsqrtf(sum);
                float c2v  = fmaf(0.5f * fabsf(dq), rr, 0.5f);
                float invc = rsqrtf(c2v);
                float sg   = copysignf(1.f, dq);
                float c    = c2v * invc;
                float s    = sg * apq * rr * invc;
                float hr   = 0.5f * sum * rr;       // r/2
                float mean = 0.5f * (app + aqq);
                float napp = mean - sg * hr;
                float naqq = mean + sg * hr;
                if (!ok) { c = 1.f; s = 0.f; napp = app; naqq = aqq; }
                nrm[p] = napp;
                nrm[q] = naqq;
                ull c2  = pack2(c, c);
                ull s2  = pack2(s, s);
                ull ns2 = pack2(-s, -s);
                #pragma unroll
                for (int rp3 = 0; rp3 < 3; ++rp3) {
                    ull gp = g2h[p][rp3], gq = g2h[q][rp3];
                    g2h[p][rp3] = fma2(c2, gp, mul2(ns2, gq));
                    g2h[q][rp3] = fma2(s2, gp, mul2(c2, gq));
                }
            }
        }
    }

    // ---- L = sum_m (log(n_m)/n_m) w_m w_m^T (redundant; halves exchanged) ----
    float Lp[WSK];
    #pragma unroll
    for (int k = 0; k < WSK; ++k) Lp[k] = 0.f;
    #pragma unroll
    for (int m = 0; m < 11; ++m) {
        float wown[6], woth[6];
        #pragma unroll
        for (int rp3 = 0; rp3 < 3; ++rp3) {
            unpack2(g2h[m][rp3], wown[2 * rp3], wown[2 * rp3 + 1]);
            ull o = __shfl_xor_sync(0xFFFFFFFFu, g2h[m][rp3], 1);
            unpack2(o, woth[2 * rp3], woth[2 * rp3 + 1]);
        }
        float w[12];
        #pragma unroll
        for (int i = 0; i < 6; ++i) {
            w[i]     = half ? woth[i] : wown[i];
            w[6 + i] = half ? wown[i] : woth[i];
        }
        float nn = 0.f;
        #pragma unroll
        for (int i = 0; i < 11; ++i) nn = fmaf(w[i], w[i], nn);
        nn = fmaxf(nn, 1e-30f);
        float sc = __fdividef(__logf(nn), nn);
        float vm[11];
        #pragma unroll
        for (int i = 0; i < 11; ++i) vm[i] = sc * w[i];
        #pragma unroll
        for (int i = 0; i < 11; ++i)
            #pragma unroll
            for (int j = i; j < 11; ++j)
                Lp[TRI(i, j)] = fmaf(vm[i], w[j], Lp[TRI(i, j)]);
    }

    // ---- linear, split 26/26 across the pair: c in [half*26, half*26+26) ----
    ull lp2[34];
    #pragma unroll
    for (int k = 0; k < 34; ++k) lp2[k] = pack2(Lp[2 * k], Lp[2 * k + 1]);

    const ulonglong2* Wv = reinterpret_cast<const ulonglong2*>(Ws);
    const int cbase = half * 26;
    float2* og = reinterpret_cast<float2*>(out + (size_t)b * 52 + cbase);
    #pragma unroll
    for (int c2i = 0; c2i < 13; ++c2i) {
        float2 rr2;
        #pragma unroll
        for (int e = 0; e < 2; ++e) {
            int c = cbase + 2 * c2i + e;
            const ulonglong2* wrow = Wv + c * 17;
            ulonglong2 w0 = wrow[0];
            ull acc0 = mul2(w0.x, lp2[0]);
            ull acc1 = mul2(w0.y, lp2[1]);
            #pragma unroll
            for (int k4 = 1; k4 < 17; ++k4) {
                ulonglong2 wk = wrow[k4];
                acc0 = fma2(wk.x, lp2[2 * k4 + 0], acc0);
                acc1 = fma2(wk.y, lp2[2 * k4 + 1], acc1);
            }
            float a0, a1, b0, b1;
            unpack2(acc0, a0, a1);
            unpack2(acc1, b0, b1);
            reinterpret_cast<float*>(&rr2)[e] = bs[c] + ((a0 + a1) + (b0 + b1));
        }
        if (live) og[c2i] = rr2;
    }
}

extern "C" void kernel_launch(void* const* d_in, const int* in_sizes, int n_in,
                              void* d_out, int out_size) {
    const float* x     = (const float*)d_in[0];
    const float* w1    = (const float*)d_in[1];
    const float* w2    = (const float*)d_in[2];
    const float* w_lin = (const float*)d_in[3];
    const float* b_lin = (const float*)d_in[4];
    float* out = (float*)d_out;

    int B = in_sizes[0] / 144;

    prep_kernel<<<1, 256>>>(w1, w2, w_lin);
    int blocks = (B + 63) / 64;       // one matrix per lane pair, 64 per block
    spd_main<<<blocks, 128>>>(x, b_lin, out, B);
}

// round 15
// speedup vs baseline: 1.5432x; 1.5432x over previous
#include <cuda_runtime.h>
#include <math.h>

// ---------------------------------------------------------------------------
// SPDNet collapsed: out = vec(logm(M^T X M)) @ Wsym + b,  M = w1 @ w2 (12x11)
// Both ReEig stages are provably no-ops (lambda_min >= 1e-3 > eps = 1e-4).
// One-sided Jacobi SVD on the Cholesky factor G (H = G G^T), two-MUFU
// rotations. R15: NSWEEP back to 5 (4 sweeps measured rel_err 1.24e-3 > 1e-3
// gate -- sweep 5 is required); KEEP the per-round batching of the 5
// independent rotations (phase A: 5 dots + (c,s) chains; phase B: 5 applies).
// ---------------------------------------------------------------------------

#define NSWEEP 5
#define WSK 68   // padded inner dim for the linear layer (66 -> 68 for float4)

typedef unsigned long long ull;

__device__ float g_M[132];            // M = w1 @ w2 (12x11)
__device__ ull   g_M2[12 * 6];        // M rows packed as f32x2 (11 -> 12 padded)
__device__ float g_Wsym[52 * WSK];    // symmetrized linear weights, padded

// upper-triangle index, requires i <= j
__device__ __forceinline__ constexpr int TRI(int i, int j) {
    return i * 11 - (i * (i + 1)) / 2 + j;
}

// ---- packed f32x2 helpers (PTX-only; ptxas never fuses these from C++) ----
__device__ __forceinline__ ull pack2(float lo, float hi) {
    ull r; asm("mov.b64 %0, {%1, %2};" : "=l"(r) : "f"(lo), "f"(hi)); return r;
}
__device__ __forceinline__ void unpack2(ull v, float& lo, float& hi) {
    asm("mov.b64 {%0, %1}, %2;" : "=f"(lo), "=f"(hi) : "l"(v));
}
__device__ __forceinline__ ull fma2(ull a, ull b, ull c) {
    ull d; asm("fma.rn.f32x2 %0, %1, %2, %3;" : "=l"(d) : "l"(a), "l"(b), "l"(c)); return d;
}
__device__ __forceinline__ ull mul2(ull a, ull b) {
    ull d; asm("mul.rn.f32x2 %0, %1, %2;" : "=l"(d) : "l"(a), "l"(b)); return d;
}

__global__ void prep_kernel(const float* __restrict__ w1,
                            const float* __restrict__ w2,
                            const float* __restrict__ w_lin) {
    __shared__ float sM[132];
    int t = threadIdx.x;
    if (t < 132) {
        int i = t / 11, l = t % 11;
        float acc = 0.f;
        #pragma unroll
        for (int k = 0; k < 12; ++k) acc += w1[i * 12 + k] * w2[k * 11 + l];
        sM[t] = acc;
        g_M[t] = acc;
    }
    __syncthreads();
    if (t < 72) {
        int j = t / 6, rp = t % 6;
        float lo = (2 * rp     < 11) ? sM[j * 11 + 2 * rp]     : 0.f;
        float hi = (2 * rp + 1 < 11) ? sM[j * 11 + 2 * rp + 1] : 0.f;
        g_M2[t] = pack2(lo, hi);
    }
    for (int idx = t; idx < 52 * WSK; idx += blockDim.x) {
        int c = idx / WSK, tt = idx % WSK;
        float v = 0.f;
        if (tt < 66) {
            int i = 0, rem = tt;
            while (rem >= 11 - i) { rem -= 11 - i; ++i; }
            int j = i + rem;
            if (i == j) v = w_lin[c * 121 + i * 11 + i];
            else        v = w_lin[c * 121 + i * 11 + j] + w_lin[c * 121 + j * 11 + i];
        }
        g_Wsym[idx] = v;
    }
}

__global__ __launch_bounds__(128, 2) void spd_main(const float* __restrict__ x,
                                                   const float* __restrict__ b_lin,
                                                   float* __restrict__ out, int B) {
    __shared__ float Ms[132];
    __shared__ ull   Ms2[72];
    __shared__ alignas(16) float Ws[52 * WSK];
    __shared__ float bs[52];
    for (int i = threadIdx.x; i < 132; i += blockDim.x) Ms[i] = g_M[i];
    for (int i = threadIdx.x; i < 72; i += blockDim.x) Ms2[i] = g_M2[i];
    for (int i = threadIdx.x; i < 52 * WSK; i += blockDim.x) Ws[i] = g_Wsym[i];
    if (threadIdx.x < 52) bs[threadIdx.x] = b_lin[threadIdx.x];
    __syncthreads();

    int b = blockIdx.x * blockDim.x + threadIdx.x;
    if (b >= B) return;

    // ---- H = M^T X M, accumulated row-incrementally into packed upper tri ----
    float h[66];
    #pragma unroll
    for (int k = 0; k < 66; ++k) h[k] = 0.f;

    const float4* xg = reinterpret_cast<const float4*>(x + (size_t)b * 144);
    #pragma unroll
    for (int i = 0; i < 12; ++i) {
        float4 v0 = xg[i * 3 + 0];
        float4 v1 = xg[i * 3 + 1];
        float4 v2 = xg[i * 3 + 2];
        float xr[12] = {v0.x, v0.y, v0.z, v0.w,
                        v1.x, v1.y, v1.z, v1.w,
                        v2.x, v2.y, v2.z, v2.w};
        // trow = X[i,:] @ M, packed over the 11(->12) output columns
        ull trow2[6];
        {
            ull xj2 = pack2(xr[0], xr[0]);
            #pragma unroll
            for (int rp = 0; rp < 6; ++rp) trow2[rp] = mul2(xj2, Ms2[0 * 6 + rp]);
        }
        #pragma unroll
        for (int j = 1; j < 12; ++j) {
            ull xj2 = pack2(xr[j], xr[j]);
            #pragma unroll
            for (int rp = 0; rp < 6; ++rp)
                trow2[rp] = fma2(xj2, Ms2[j * 6 + rp], trow2[rp]);
        }
        float trow[12];
        #pragma unroll
        for (int rp = 0; rp < 6; ++rp) unpack2(trow2[rp], trow[2 * rp], trow[2 * rp + 1]);
        #pragma unroll
        for (int k = 0; k < 11; ++k) {
            float mik = Ms[i * 11 + k];
            #pragma unroll
            for (int l = k; l < 11; ++l)
                h[TRI(k, l)] = fmaf(mik, trow[l], h[TRI(k, l)]);
        }
    }

    // ---- Cholesky H = R^T R fused with G = R^T packing: row k of R becomes
    //      column k of G immediately, so h rows die as g2 rows are born. ----
    ull g2[11][6];
    float nrm[11];
    #pragma unroll
    for (int k = 0; k < 11; ++k) {
        float d   = fmaxf(h[TRI(k, k)], 1e-30f);
        float inv = rsqrtf(d);
        float rk[11];
        #pragma unroll
        for (int j = 0; j < 11; ++j) rk[j] = 0.f;
        rk[k] = d * inv;
        #pragma unroll
        for (int j = k + 1; j < 11; ++j) rk[j] = h[TRI(k, j)] * inv;
        float acc = d;   // rk[k]^2 = d
        #pragma unroll
        for (int j = k + 1; j < 11; ++j) acc = fmaf(rk[j], rk[j], acc);
        nrm[k] = acc;
        #pragma unroll
        for (int rp = 0; rp < 6; ++rp)
            g2[k][rp] = pack2(rk[2 * rp], (2 * rp + 1 < 11) ? rk[2 * rp + 1] : 0.f);
        #pragma unroll
        for (int j = k + 1; j < 11; ++j) {
            float a = rk[j];
            #pragma unroll
            for (int l = j; l < 11; ++l)
                h[TRI(j, l)] = fmaf(-a, rk[l], h[TRI(j, l)]);
        }
    }

    // ---- one-sided Jacobi, round-robin; per round: batch the 5 independent
    //      dots + (c,s) chains (phase A), then apply the 5 rotations (B). ----
    for (int sweep = 0; sweep < NSWEEP; ++sweep) {
        #pragma unroll
        for (int r = 0; r < 11; ++r) {
            const int mm = (r * 6) % 11;  // bye element; pairs (mm+k, mm-k)
            float cs_c[5], cs_s[5];
            // -- phase A: all reads of g2 precede all writes (pairs disjoint) --
            #pragma unroll
            for (int k = 1; k <= 5; ++k) {
                const int a0 = (mm + k) % 11;
                const int b0 = (mm + 11 - k) % 11;
                const int p = (a0 < b0) ? a0 : b0;
                const int q = (a0 < b0) ? b0 : a0;
                ull acc = mul2(g2[p][0], g2[q][0]);
                #pragma unroll
                for (int rp = 1; rp < 6; ++rp) acc = fma2(g2[p][rp], g2[q][rp], acc);
                float dlo, dhi;
                unpack2(acc, dlo, dhi);
                float apq = dlo + dhi;
                float app = nrm[p], aqq = nrm[q];
                float dq   = aqq - app;
                float sum  = fmaf(dq, dq, 4.f * apq * apq);
                bool  ok   = sum > 1e-30f;
                float rr   = rsqrtf(sum);
                float c2v  = fmaf(0.5f * fabsf(dq), rr, 0.5f);
                float invc = rsqrtf(c2v);
                float sg   = copysignf(1.f, dq);
                float c    = c2v * invc;
                float s    = sg * apq * rr * invc;
                float hr   = 0.5f * sum * rr;       // r/2
                float mean = 0.5f * (app + aqq);
                float napp = mean - sg * hr;
                float naqq = mean + sg * hr;
                if (!ok) { c = 1.f; s = 0.f; napp = app; naqq = aqq; }
                nrm[p] = napp;
                nrm[q] = naqq;
                cs_c[k - 1] = c;
                cs_s[k - 1] = s;
            }
            // -- phase B: apply all 5 column rotations --
            #pragma unroll
            for (int k = 1; k <= 5; ++k) {
                const int a0 = (mm + k) % 11;
                const int b0 = (mm + 11 - k) % 11;
                const int p = (a0 < b0) ? a0 : b0;
                const int q = (a0 < b0) ? b0 : a0;
                const float c = cs_c[k - 1];
                const float s = cs_s[k - 1];
                ull c2  = pack2(c, c);
                ull s2  = pack2(s, s);
                ull ns2 = pack2(-s, -s);
                #pragma unroll
                for (int rp = 0; rp < 6; ++rp) {
                    ull gp = g2[p][rp], gq = g2[q][rp];
                    g2[p][rp] = fma2(c2, gp, mul2(ns2, gq));
                    g2[q][rp] = fma2(s2, gp, mul2(c2, gq));
                }
            }
        }
    }

    // ---- L = sum_m (log(n_m)/n_m) w_m w_m^T, n_m = |w_m|^2 (exact recompute) ----
    float Lp[WSK];
    #pragma unroll
    for (int k = 0; k < WSK; ++k) Lp[k] = 0.f;
    #pragma unroll
    for (int m = 0; m < 11; ++m) {
        float w[12];
        #pragma unroll
        for (int rp = 0; rp < 6; ++rp) unpack2(g2[m][rp], w[2 * rp], w[2 * rp + 1]);
        float nn = 0.f;
        #pragma unroll
        for (int i = 0; i < 11; ++i) nn = fmaf(w[i], w[i], nn);
        nn = fmaxf(nn, 1e-30f);
        float sc = __fdividef(__logf(nn), nn);
        float vm[11];
        #pragma unroll
        for (int i = 0; i < 11; ++i) vm[i] = sc * w[i];
        #pragma unroll
        for (int i = 0; i < 11; ++i)
            #pragma unroll
            for (int j = i; j < 11; ++j)
                Lp[TRI(i, j)] = fmaf(vm[i], w[j], Lp[TRI(i, j)]);
    }

    // ---- linear: out[b][c] = b[c] + Ws[c][:] . Lp, packed f32x2 ----
    ull lp2[34];
    #pragma unroll
    for (int k = 0; k < 34; ++k) lp2[k] = pack2(Lp[2 * k], Lp[2 * k + 1]);

    const ulonglong2* Wv = reinterpret_cast<const ulonglong2*>(Ws);
    float4* og = reinterpret_cast<float4*>(out + (size_t)b * 52);
    #pragma unroll
    for (int c4 = 0; c4 < 13; ++c4) {
        float4 rr4;
        #pragma unroll
        for (int e = 0; e < 4; ++e) {
            int c = c4 * 4 + e;
            const ulonglong2* wrow = Wv + c * 17;
            ulonglong2 w0 = wrow[0];
            ull acc0 = mul2(w0.x, lp2[0]);
            ull acc1 = mul2(w0.y, lp2[1]);
            #pragma unroll
            for (int k4 = 1; k4 < 17; ++k4) {
                ulonglong2 wk = wrow[k4];
                acc0 = fma2(wk.x, lp2[2 * k4 + 0], acc0);
                acc1 = fma2(wk.y, lp2[2 * k4 + 1], acc1);
            }
            float a0, a1, b0, b1;
            unpack2(acc0, a0, a1);
            unpack2(acc1, b0, b1);
            reinterpret_cast<float*>(&rr4)[e] = bs[c] + ((a0 + a1) + (b0 + b1));
        }
        og[c4] = rr4;
    }
}

extern "C" void kernel_launch(void* const* d_in, const int* in_sizes, int n_in,
                              void* d_out, int out_size) {
    const float* x     = (const float*)d_in[0];
    const float* w1    = (const float*)d_in[1];
    const float* w2    = (const float*)d_in[2];
    const float* w_lin = (const float*)d_in[3];
    const float* b_lin = (const float*)d_in[4];
    float* out = (float*)d_out;

    int B = in_sizes[0] / 144;

    prep_kernel<<<1, 256>>>(w1, w2, w_lin);
    int threads = 128;
    int blocks  = (B + threads - 1) / threads;
    spd_main<<<blocks, threads>>>(x, b_lin, out, B);
}